// round 10
// baseline (speedup 1.0000x reference)
#include <cuda_runtime.h>
#include <cuda_fp16.h>
#include <math.h>

#define NCH 256

// fp16 transposed [H,W,C] scratch for levels 3..5 (10.5 MB, L2-resident).
// Level 2 (~1.4% of boxes) is gathered directly from raw [C,H,W] fp32 p2.
__device__ __align__(16) __half g_t3[128 * 128 * NCH];  //  8 MB
__device__ __align__(16) __half g_t4[64 * 64 * NCH];    //  2 MB
__device__ __align__(16) __half g_t5[32 * 32 * NCH];    // 0.5 MB

#define NB3T 2048
#define NB4T 512
#define NB5T 128
#define NBT  (NB3T + NB4T + NB5T)

__global__ __launch_bounds__(256) void transpose345(
    const float* __restrict__ p3, const float* __restrict__ p4,
    const float* __restrict__ p5)
{
    __shared__ float tile[64][33];

    int bid = blockIdx.x;
    const float* __restrict__ in;
    __half* __restrict__ out;
    int HW;
    if (bid < NB3T)              { in = p3; out = g_t3; HW = 16384; }
    else if (bid < NB3T + NB4T)  { bid -= NB3T;        in = p4; out = g_t4; HW = 4096; }
    else                         { bid -= NB3T + NB4T; in = p5; out = g_t5; HW = 1024; }

    const int nhw = HW >> 5;
    const int hw0 = (bid % nhw) * 32;
    const int c0  = (bid / nhw) * 64;
    const int t = threadIdx.x;

    // Load: float4 per thread, 64 rows x 128B.
    const int r0 = t >> 3;          // 0..31
    const int c4 = (t & 7) * 4;     // 0,4,..,28
#pragma unroll
    for (int rr = 0; rr < 64; rr += 32) {
        const float4 v = *reinterpret_cast<const float4*>(
            &in[(size_t)(c0 + r0 + rr) * HW + hw0 + c4]);
        tile[r0 + rr][c4 + 0] = v.x;
        tile[r0 + rr][c4 + 1] = v.y;
        tile[r0 + rr][c4 + 2] = v.z;
        tile[r0 + rr][c4 + 3] = v.w;
    }
    __syncthreads();

    // Store: warp writes 32 half2 = 128B contiguous along C.
    const int tx = t & 31, ty = t >> 5;   // ty 0..7
#pragma unroll
    for (int hh = ty; hh < 32; hh += 8) {
        __half2 v = __floats2half2_rn(tile[2 * tx][hh], tile[2 * tx + 1][hh]);
        *reinterpret_cast<__half2*>(&out[(size_t)(hw0 + hh) * NCH + c0 + 2 * tx]) = v;
    }
}

// 4 blocks per box: blockIdx = box*4 + chunk (64 channels, all 49 samples).
// Phase 1: threads 0..48 precompute per-sample neighbor offsets + fused
// bilinear weights into smem.
// Phase 2: warp = 16 channel-quads x samples, LDG.64 loads (one full 128B
// line per sample across 16 threads). Loads for TWO samples are batched
// before any consumption (launch_bounds(256,4) -> 64-reg budget) so each
// warp keeps >=8 loads in flight; R9 at 32 regs was scoreboard-bound at
// ~4 in flight (issue 48%, occ 85%, no pipe above 50%).
__global__ __launch_bounds__(256, 4) void roi_gather(
    const float* __restrict__ boxes, const float* __restrict__ p2,
    float* __restrict__ out)
{
    __shared__ float  sm[64 * 49];   // 12544 B staging, [c][s]
    __shared__ int4   offs[49];      // neighbor offsets (00,10,01,11)
    __shared__ float4 wts[49];       // fused weights  (w00,w10,w01,w11)

    const int b = blockIdx.x >> 2;
    const int q = blockIdx.x & 3;    // channel chunk: channels [64q, 64q+64)

    const float y1 = boxes[4 * b + 0];
    const float x1 = boxes[4 * b + 1];
    const float y2 = boxes[4 * b + 2];
    const float x2 = boxes[4 * b + 3];
    const float h = y2 - y1;
    const float w = x2 - x1;

    const float lvl = 4.0f + log2f(sqrtf(h * w) / 0.21875f);
    int level = (int)rintf(lvl);
    level = min(5, max(2, level));

    const __half* __restrict__ fm16 = g_t5;
    int H = 32;
    if      (level == 2) { H = 256; }
    else if (level == 3) { fm16 = g_t3; H = 128; }
    else if (level == 4) { fm16 = g_t4; H = 64;  }
    const int W = H;
    const float Hm1 = (float)(H - 1);
    const int mul = (level == 2) ? 1 : NCH;   // offset units

    const int t = threadIdx.x;

    // ---- Phase 1: per-sample geometry (one thread per sample) ----
    if (t < 49) {
        const int py = t / 7;
        const int px = t - 7 * py;
        const float ys = (y1 + (float)py * (1.0f / 6.0f) * h) * Hm1;
        const float xs = (x1 + (float)px * (1.0f / 6.0f) * w) * Hm1;
        const float y0f = floorf(ys);
        const float x0f = floorf(xs);
        const float ly = ys - y0f;
        const float lx = xs - x0f;
        const int y0  = min(H - 1, max(0, (int)y0f));
        const int x0  = min(W - 1, max(0, (int)x0f));
        const int y1i = min(H - 1, y0 + 1);
        const int x1i = min(W - 1, x0 + 1);
        const float vv = ((ys >= 0.0f && ys <= Hm1) ? 1.0f : 0.0f) *
                         ((xs >= 0.0f && xs <= Hm1) ? 1.0f : 0.0f);
        const float wy0 = 1.0f - ly, wy1 = ly;
        const float wx0 = 1.0f - lx, wx1 = lx;
        offs[t] = make_int4((y0  * W + x0 ) * mul, (y1i * W + x0 ) * mul,
                            (y0  * W + x1i) * mul, (y1i * W + x1i) * mul);
        wts[t]  = make_float4(wy0 * wx0 * vv, wy1 * wx0 * vv,
                              wy0 * wx1 * vv, wy1 * wx1 * vv);
    }
    __syncthreads();

    // ---- Phase 2: gather. quad p = t&15 (channels 4p..4p+3), sg = t>>4. ----
    const int p  = t & 15;
    const int sg = t >> 4;            // 0..15
    const int cl = 4 * p;             // local channel base within chunk

    if (level != 2) {
        const __half* __restrict__ base = fm16 + 64 * q + cl;
        // Two pair-batched passes: samples {sg, sg+16} then {sg+32, sg+48}.
#pragma unroll
        for (int pass = 0; pass < 2; pass++) {
            const int s0 = sg + 32 * pass;
            const int s1 = s0 + 16;
            const bool a0 = (s0 < 49);
            const bool a1 = (s1 < 49);

            int4   o0, o1;
            float4 w0, w1;
            float2 u00, u10, u01, u11;      // sample 0 neighbors
            float2 z00, z10, z01, z11;      // sample 1 neighbors

            if (a0) {
                o0 = offs[s0]; w0 = wts[s0];
                u00 = *reinterpret_cast<const float2*>(base + o0.x);
                u10 = *reinterpret_cast<const float2*>(base + o0.y);
                u01 = *reinterpret_cast<const float2*>(base + o0.z);
                u11 = *reinterpret_cast<const float2*>(base + o0.w);
            }
            if (a1) {
                o1 = offs[s1]; w1 = wts[s1];
                z00 = *reinterpret_cast<const float2*>(base + o1.x);
                z10 = *reinterpret_cast<const float2*>(base + o1.y);
                z01 = *reinterpret_cast<const float2*>(base + o1.z);
                z11 = *reinterpret_cast<const float2*>(base + o1.w);
            }

            if (a0) {
                const float2 a00 = __half22float2(*reinterpret_cast<const __half2*>(&u00.x));
                const float2 b00 = __half22float2(*reinterpret_cast<const __half2*>(&u00.y));
                const float2 a10 = __half22float2(*reinterpret_cast<const __half2*>(&u10.x));
                const float2 b10 = __half22float2(*reinterpret_cast<const __half2*>(&u10.y));
                const float2 a01 = __half22float2(*reinterpret_cast<const __half2*>(&u01.x));
                const float2 b01 = __half22float2(*reinterpret_cast<const __half2*>(&u01.y));
                const float2 a11 = __half22float2(*reinterpret_cast<const __half2*>(&u11.x));
                const float2 b11 = __half22float2(*reinterpret_cast<const __half2*>(&u11.y));
                sm[(cl + 0) * 49 + s0] = a00.x * w0.x + a10.x * w0.y + a01.x * w0.z + a11.x * w0.w;
                sm[(cl + 1) * 49 + s0] = a00.y * w0.x + a10.y * w0.y + a01.y * w0.z + a11.y * w0.w;
                sm[(cl + 2) * 49 + s0] = b00.x * w0.x + b10.x * w0.y + b01.x * w0.z + b11.x * w0.w;
                sm[(cl + 3) * 49 + s0] = b00.y * w0.x + b10.y * w0.y + b01.y * w0.z + b11.y * w0.w;
            }
            if (a1) {
                const float2 a00 = __half22float2(*reinterpret_cast<const __half2*>(&z00.x));
                const float2 b00 = __half22float2(*reinterpret_cast<const __half2*>(&z00.y));
                const float2 a10 = __half22float2(*reinterpret_cast<const __half2*>(&z10.x));
                const float2 b10 = __half22float2(*reinterpret_cast<const __half2*>(&z10.y));
                const float2 a01 = __half22float2(*reinterpret_cast<const __half2*>(&z01.x));
                const float2 b01 = __half22float2(*reinterpret_cast<const __half2*>(&z01.y));
                const float2 a11 = __half22float2(*reinterpret_cast<const __half2*>(&z11.x));
                const float2 b11 = __half22float2(*reinterpret_cast<const __half2*>(&z11.y));
                sm[(cl + 0) * 49 + s1] = a00.x * w1.x + a10.x * w1.y + a01.x * w1.z + a11.x * w1.w;
                sm[(cl + 1) * 49 + s1] = a00.y * w1.x + a10.y * w1.y + a01.y * w1.z + a11.y * w1.w;
                sm[(cl + 2) * 49 + s1] = b00.x * w1.x + b10.x * w1.y + b01.x * w1.z + b11.x * w1.w;
                sm[(cl + 3) * 49 + s1] = b00.y * w1.x + b10.y * w1.y + b01.y * w1.z + b11.y * w1.w;
            }
        }
    } else {
        const float* __restrict__ bbase = p2 + (size_t)(64 * q + cl) * 65536;
#pragma unroll
        for (int i = 0; i < 4; i++) {
            const int s = sg + 16 * i;
            if (s < 49) {
                const int4   o  = offs[s];
                const float4 wv = wts[s];
#pragma unroll
                for (int j = 0; j < 4; j++) {
                    const float* __restrict__ bj = bbase + (size_t)j * 65536;
                    sm[(cl + j) * 49 + s] =
                        bj[o.x] * wv.x + bj[o.y] * wv.y +
                        bj[o.z] * wv.z + bj[o.w] * wv.w;
                }
            }
        }
    }
    __syncthreads();

    // Chunk output is contiguous: out[b][64q..64q+64][49] = 3136 floats.
    const float4* __restrict__ sm4 = reinterpret_cast<const float4*>(sm);
    float4* __restrict__ ob =
        reinterpret_cast<float4*>(out + (size_t)b * (NCH * 49) + (size_t)q * (64 * 49));
#pragma unroll
    for (int i = t; i < 784; i += 256)
        ob[i] = sm4[i];
}

extern "C" void kernel_launch(void* const* d_in, const int* in_sizes, int n_in,
                              void* d_out, int out_size)
{
    const float* boxes = (const float*)d_in[0];
    const float* p2    = (const float*)d_in[1];
    const float* p3    = (const float*)d_in[2];
    const float* p4    = (const float*)d_in[3];
    const float* p5    = (const float*)d_in[4];
    float* out = (float*)d_out;

    transpose345<<<NBT, 256>>>(p3, p4, p5);

    const int nboxes = in_sizes[0] / 4;
    roi_gather<<<4 * nboxes, 256>>>(boxes, p2, out);
}